// round 16
// baseline (speedup 1.0000x reference)
#include <cuda_runtime.h>
#include <cuda_fp16.h>
#include <stdint.h>

// Problem constants (fixed shapes)
#define M_NODES   131072
#define K_DIM     256
#define N_PROJ    256
#define NUM_G     256
#define NPG       512          // nodes per graph
#define NUM_Q     256
#define NCHUNK    8            // pipeline chunks (32 graphs each)

// Scratch (device globals; no allocation allowed in kernel_launch)
__device__ __half  g_bh[N_PROJ * K_DIM];                       // proj^T fp16 [n][k]
__device__ __half2 g_xpt2[(size_t)NUM_G * 128 * NPG];          // paired cols [g][p2][i]

// ---------------------------------------------------------------------------
// PTX helpers (base ISA only — no sm_103a-gated features)
// ---------------------------------------------------------------------------
__device__ __forceinline__ uint32_t smem_u32(const void* p) {
    uint32_t a;
    asm("{ .reg .u64 t; cvta.to.shared.u64 t, %1; cvt.u32.u64 %0, t; }" : "=r"(a) : "l"(p));
    return a;
}
__device__ __forceinline__ void cp_async16(uint32_t saddr, const void* gptr) {
    asm volatile("cp.async.cg.shared.global [%0], [%1], 16;" :: "r"(saddr), "l"(gptr));
}
__device__ __forceinline__ void cp_commit() { asm volatile("cp.async.commit_group;"); }
__device__ __forceinline__ void cp_wait1()  { asm volatile("cp.async.wait_group 1;"); }
__device__ __forceinline__ void cp_wait0()  { asm volatile("cp.async.wait_group 0;"); }

__device__ __forceinline__ void ldsm4(uint32_t& r0, uint32_t& r1, uint32_t& r2, uint32_t& r3,
                                      uint32_t addr) {
    asm volatile("ldmatrix.sync.aligned.m8n8.x4.shared.b16 {%0,%1,%2,%3}, [%4];"
                 : "=r"(r0), "=r"(r1), "=r"(r2), "=r"(r3) : "r"(addr));
}
__device__ __forceinline__ void mma_fp16(float* c, const uint32_t* a, uint32_t b0, uint32_t b1) {
    asm volatile("mma.sync.aligned.m16n8k16.row.col.f32.f16.f16.f32 "
                 "{%0,%1,%2,%3}, {%4,%5,%6,%7}, {%8,%9}, {%0,%1,%2,%3};"
                 : "+f"(c[0]), "+f"(c[1]), "+f"(c[2]), "+f"(c[3])
                 : "r"(a[0]), "r"(a[1]), "r"(a[2]), "r"(a[3]), "r"(b0), "r"(b1));
}

// ---------------------------------------------------------------------------
// Kernel 1: convert + transpose proj -> B[n][k] fp16 (K-major); tiny.
// ---------------------------------------------------------------------------
__global__ void convp_kernel(const float* __restrict__ proj) {
    int n = blockIdx.x, k = threadIdx.x;
    g_bh[n * K_DIM + k] = __float2half_rn(proj[(size_t)k * N_PROJ + n]);
}

// ---------------------------------------------------------------------------
// Kernel 2: single-pass fp16 HMMA GEMM, BM=64 BN=256 BK=64.
//   Epilogue converts to fp16 and writes PAIRED half2 columns into g_xpt2.
// ---------------------------------------------------------------------------
#define BM 64
#define BN 256
#define BK 64
#define GTHREADS 256
#define S_BOP   16384
#define GEMM_SMEM 81920
#define EPAD 68

__global__ void __launch_bounds__(GTHREADS, 2)
gemm_hmma_kernel(const float* __restrict__ x, int tbase) {
    extern __shared__ char smem[];
    const uint32_t sb = smem_u32(smem);

    const int t     = threadIdx.x;
    const int lane  = t & 31;
    const int wid   = t >> 5;
    const int tb    = tbase + blockIdx.x;
    const int mBase = tb * BM;
    const int wm    = (wid >> 2) * 32;   // warp tile 32 x 64
    const int wn    = (wid & 3) * 64;

    const int rsel  = lane & 15;
    const int khalf = lane >> 4;
    const int kx    = lane & 7;

    uint32_t mByte[2], nByte[4];
#pragma unroll
    for (int mi = 0; mi < 2; mi++) mByte[mi] = (uint32_t)(wm + mi * 16 + rsel) * 128;
#pragma unroll
    for (int ni = 0; ni < 4; ni++) nByte[ni] = (uint32_t)(wn + ni * 16 + rsel) * 128;

    int aRow[2], aG[2];
    uint32_t aSw[2];
#pragma unroll
    for (int h = 0; h < 2; h++) {
        int u = t + 256 * h;
        aRow[h] = u >> 3;
        aG[h]   = u & 7;
        aSw[h]  = (uint32_t)(aRow[h] * 128 + ((aG[h] ^ (aRow[h] & 7)) << 4));
    }

    float aF[16];
    auto ldgA = [&](int c) {
#pragma unroll
        for (int h = 0; h < 2; h++) {
            const float4* p = (const float4*)(x + (size_t)(mBase + aRow[h]) * K_DIM
                                              + c * BK + aG[h] * 8);
            float4 u0 = p[0], u1 = p[1];
            aF[h*8+0] = u0.x; aF[h*8+1] = u0.y; aF[h*8+2] = u0.z; aF[h*8+3] = u0.w;
            aF[h*8+4] = u1.x; aF[h*8+5] = u1.y; aF[h*8+6] = u1.z; aF[h*8+7] = u1.w;
        }
    };
    auto stsA = [&](int buf) {
#pragma unroll
        for (int h = 0; h < 2; h++) {
            uint32_t pk[4];
#pragma unroll
            for (int j = 0; j < 4; j++) {
                __half2 hh = __floats2half2_rn(aF[h*8 + 2*j], aF[h*8 + 2*j + 1]);
                pk[j] = *(uint32_t*)&hh;
            }
            *(uint4*)(smem + buf * 8192 + aSw[h]) = make_uint4(pk[0], pk[1], pk[2], pk[3]);
        }
    };
    auto cpB = [&](int c) {
        const int kB = c * BK;
        const uint32_t bufB = sb + S_BOP + (c & 1) * 32768;
#pragma unroll
        for (int r = 0; r < 8; r++) {
            int u   = t + GTHREADS * r;
            int row = u >> 3;
            int gg  = u & 7;
            uint32_t sw = (uint32_t)(row * 128 + ((gg ^ (row & 7)) << 4));
            cp_async16(bufB + sw, g_bh + (size_t)row * K_DIM + kB + gg * 8);
        }
        cp_commit();
    };

    float acc[2][8][4];
#pragma unroll
    for (int mi = 0; mi < 2; mi++)
#pragma unroll
        for (int ni = 0; ni < 8; ni++)
#pragma unroll
            for (int r = 0; r < 4; r++) acc[mi][ni][r] = 0.0f;

    ldgA(0);
    cpB(0);
    cpB(1);
    stsA(0);
    ldgA(1);

    const int NCH = K_DIM / BK;   // 4
    for (int c = 0; c < NCH; c++) {
        if (c < NCH - 1) cp_wait1(); else cp_wait0();
        __syncthreads();

        if (c + 1 < NCH) stsA((c + 1) & 1);
        if (c + 2 < NCH) ldgA(c + 2);

        const uint32_t bufA = sb + (c & 1) * 8192;
        const uint32_t bufB = sb + S_BOP + (c & 1) * 32768;

#pragma unroll
        for (int ks = 0; ks < 4; ks++) {
            const uint32_t seg = (uint32_t)((ks * 2 + khalf) ^ kx) << 4;

            uint32_t ah[2][4], bh[4][4];
#pragma unroll
            for (int mi = 0; mi < 2; mi++)
                ldsm4(ah[mi][0], ah[mi][1], ah[mi][2], ah[mi][3], bufA + mByte[mi] + seg);
#pragma unroll
            for (int ni = 0; ni < 4; ni++)
                ldsm4(bh[ni][0], bh[ni][1], bh[ni][2], bh[ni][3], bufB + nByte[ni] + seg);

#pragma unroll
            for (int mi = 0; mi < 2; mi++)
#pragma unroll
                for (int ni = 0; ni < 8; ni++)
                    mma_fp16(acc[mi][ni], ah[mi], bh[ni >> 1][ni & 1], bh[ni >> 1][(ni & 1) + 2]);
        }

        __syncthreads();
        if (c + 2 < NCH) cpB(c + 2);
    }

    // Epilogue: stage D transposed in smem [n][m] fp32 (stride EPAD)
    float* sOut = (float*)smem;
    const int crow = lane >> 2;
    const int ccol = (lane & 3) * 2;
#pragma unroll
    for (int mi = 0; mi < 2; mi++)
#pragma unroll
        for (int ni = 0; ni < 8; ni++) {
            int m0 = wm + mi * 16 + crow;
            int n0 = wn + ni * 8 + ccol;
            sOut[(n0    ) * EPAD + m0    ] = acc[mi][ni][0];
            sOut[(n0 + 1) * EPAD + m0    ] = acc[mi][ni][1];
            sOut[(n0    ) * EPAD + m0 + 8] = acc[mi][ni][2];
            sOut[(n0 + 1) * EPAD + m0 + 8] = acc[mi][ni][3];
        }
    __syncthreads();

    // Paired fp16 write: g_xpt2[(g*128 + p2)*512 + i] = (D[2p2][i], D[2p2+1][i])
    const int g     = mBase >> 9;
    const int iBase = mBase & 511;
#pragma unroll
    for (int r = 0; r < 8; r++) {
        int u  = t + GTHREADS * r;          // 0..2047
        int p2 = u >> 4;                    // 0..127
        int i4 = (u & 15) * 4;              // 0..60
        const float* r0 = &sOut[(2 * p2    ) * EPAD + i4];
        const float* r1 = &sOut[(2 * p2 + 1) * EPAD + i4];
        __half2 h0 = __floats2half2_rn(r0[0], r1[0]);
        __half2 h1 = __floats2half2_rn(r0[1], r1[1]);
        __half2 h2 = __floats2half2_rn(r0[2], r1[2]);
        __half2 h3 = __floats2half2_rn(r0[3], r1[3]);
        __half2* dst = g_xpt2 + ((size_t)(g * 128 + p2)) * NPG + iBase + i4;
        *(uint4*)dst = make_uint4(*(uint32_t*)&h0, *(uint32_t*)&h1,
                                  *(uint32_t*)&h2, *(uint32_t*)&h3);
    }
}

// ---------------------------------------------------------------------------
// Kernel 3: packed half2 bitonic sort (one column-pair per warp), loading the
//   pre-paired g_xpt2 directly (no conversion/packing on load).
// ---------------------------------------------------------------------------
__device__ __forceinline__ __half2 h2min(__half2 a, __half2 b) { return __hmin2(a, b); }
__device__ __forceinline__ __half2 h2max(__half2 a, __half2 b) { return __hmax2(a, b); }

template<int KK, int J>
__device__ __forceinline__ void bstep2(__half2 (&v)[16], int lane) {
    if constexpr (J >= 16) {
#pragma unroll
        for (int r = 0; r < 16; r++) {
            uint32_t pv = __shfl_xor_sync(0xffffffffu, *(uint32_t*)&v[r], J >> 4);
            __half2 p = *(__half2*)&pv;
            int i = lane * 16 + r;
            bool takeMin = ((i & KK) == 0) == ((i & J) == 0);
            v[r] = takeMin ? h2min(v[r], p) : h2max(v[r], p);
        }
    } else {
#pragma unroll
        for (int r = 0; r < 16; r++) {
            if ((r & J) == 0) {
                int i = lane * 16 + r;
                bool up = ((i & KK) == 0);
                __half2 a = v[r], b = v[r | J];
                v[r]     = up ? h2min(a, b) : h2max(a, b);
                v[r | J] = up ? h2max(a, b) : h2min(a, b);
            }
        }
    }
}
template<int KK, int J>
__device__ __forceinline__ void bmerge2(__half2 (&v)[16], int lane) {
    bstep2<KK, J>(v, lane);
    if constexpr (J > 1) bmerge2<KK, J / 2>(v, lane);
}

__global__ void __launch_bounds__(256)
sort_quant_kernel(const float* __restrict__ cw, float* __restrict__ out, int ubase) {
    __shared__ uint32_t sbuf[8][512];   // sorted half2 column-pairs, one per warp
    __shared__ uint32_t qbuf[8][264];   // half2 quantiles staged (padded stride)
    __shared__ int      qidx[NUM_Q];

    const int t = threadIdx.x;
    qidx[t] = (int)floorf(cw[t] * (float)(NPG - 1));   // matches jnp.floor(cw*511)
    __syncthreads();

    const int w    = t >> 5;
    const int lane = t & 31;
    const int unit = ubase + blockIdx.x;               // 16 columns (8 pairs) per unit
    const int p2   = unit * 8 + w;                     // this warp's column pair

    // Direct load of paired fp16 data (element i = lane*16 + r)
    __half2 v[16];
    const uint4* src = (const uint4*)(g_xpt2 + (size_t)p2 * NPG);
#pragma unroll
    for (int q = 0; q < 4; q++) {
        uint4 d = src[lane * 4 + q];
        v[q * 4 + 0] = *(__half2*)&d.x;
        v[q * 4 + 1] = *(__half2*)&d.y;
        v[q * 4 + 2] = *(__half2*)&d.z;
        v[q * 4 + 3] = *(__half2*)&d.w;
    }

    bmerge2<2, 1>(v, lane);
    bmerge2<4, 2>(v, lane);
    bmerge2<8, 4>(v, lane);
    bmerge2<16, 8>(v, lane);
    bmerge2<32, 16>(v, lane);
    bmerge2<64, 32>(v, lane);
    bmerge2<128, 64>(v, lane);
    bmerge2<256, 128>(v, lane);
    bmerge2<512, 256>(v, lane);

    uint4* dst = (uint4*)sbuf[w];
#pragma unroll
    for (int q = 0; q < 4; q++)
        dst[lane * 4 + q] = make_uint4(*(uint32_t*)&v[q * 4 + 0], *(uint32_t*)&v[q * 4 + 1],
                                       *(uint32_t*)&v[q * 4 + 2], *(uint32_t*)&v[q * 4 + 3]);
    __syncwarp();

#pragma unroll
    for (int s = 0; s < 8; s++) {
        int q = lane + 32 * s;
        qbuf[w][q] = sbuf[w][qidx[q]];
    }
    __syncthreads();

    // Coalesced write: out[g*65536 + q*256 + p], 16 consecutive p per CTA
    const int gg    = unit >> 4;
    const int pbase = (unit * 16) & 255;
    const size_t obase = (size_t)gg * (NUM_Q * N_PROJ) + pbase;
#pragma unroll
    for (int s = 0; s < 16; s++) {
        int e  = t + 256 * s;          // 0..4095
        int q  = e >> 4;
        int wp = e & 15;
        uint32_t pair = qbuf[wp >> 1][q];
        __half h = (wp & 1) ? __high2half(*(__half2*)&pair) : __low2half(*(__half2*)&pair);
        out[obase + (size_t)q * N_PROJ + wp] = __half2float(h) * (1.0f / 256.0f);
    }
}

// ---------------------------------------------------------------------------
// kernel_launch: convp -> chunked {gemm on legacy stream, sort on side stream}
//   pipeline with event forking (graph-capturable multi-stream pattern).
// ---------------------------------------------------------------------------
extern "C" void kernel_launch(void* const* d_in, const int* in_sizes, int n_in,
                              void* d_out, int out_size) {
    const float* x    = (const float*)d_in[0];   // [131072, 256] f32
    const float* proj = (const float*)d_in[1];   // [256, 256]    f32
    const float* cw   = (const float*)d_in[2];   // [256]         f32
    float* out = (float*)d_out;                  // [256, 65536]  f32

    cudaFuncSetAttribute(gemm_hmma_kernel,
                         cudaFuncAttributeMaxDynamicSharedMemorySize,
                         GEMM_SMEM);

    // Fresh stream/events each call (kernel_launch runs only a few times;
    // graph replays execute captured nodes, not this function). No device
    // memory is allocated by these handles.
    cudaStream_t sB;
    cudaStreamCreateWithFlags(&sB, cudaStreamNonBlocking);
    cudaEvent_t evF, evJ, evG[NCHUNK];
    cudaEventCreateWithFlags(&evF, cudaEventDisableTiming);
    cudaEventCreateWithFlags(&evJ, cudaEventDisableTiming);
    for (int i = 0; i < NCHUNK; i++)
        cudaEventCreateWithFlags(&evG[i], cudaEventDisableTiming);

    const int TPC = (M_NODES / BM) / NCHUNK;             // gemm tiles per chunk (256)
    const int UPC = ((NUM_G * N_PROJ) / 16) / NCHUNK;    // sort units per chunk (512)

    convp_kernel<<<N_PROJ, K_DIM>>>(proj);
    cudaEventRecord(evF, 0);
    cudaStreamWaitEvent(sB, evF, 0);                     // fork side stream into capture

    for (int i = 0; i < NCHUNK; i++) {
        gemm_hmma_kernel<<<TPC, GTHREADS, GEMM_SMEM>>>(x, i * TPC);
        cudaEventRecord(evG[i], 0);
        cudaStreamWaitEvent(sB, evG[i], 0);
        sort_quant_kernel<<<UPC, 256, 0, sB>>>(cw, out, i * UPC);
    }

    cudaEventRecord(evJ, sB);
    cudaStreamWaitEvent(0, evJ, 0);                      // join back to legacy stream
}

// round 17
// speedup vs baseline: 1.2822x; 1.2822x over previous
#include <cuda_runtime.h>
#include <cuda_fp16.h>
#include <stdint.h>

// Problem constants (fixed shapes)
#define M_NODES   131072
#define K_DIM     256
#define N_PROJ    256
#define NUM_G     256
#define NPG       512          // nodes per graph
#define NUM_Q     256

// Scratch (device globals; no allocation allowed in kernel_launch)
__device__ __half  g_bh[N_PROJ * K_DIM];                       // proj^T fp16 [n][k]
__device__ __half2 g_xpt2[(size_t)NUM_G * 128 * NPG];          // paired cols [g][p2][i]

// ---------------------------------------------------------------------------
// PTX helpers (base ISA only — no sm_103a-gated features)
// ---------------------------------------------------------------------------
__device__ __forceinline__ uint32_t smem_u32(const void* p) {
    uint32_t a;
    asm("{ .reg .u64 t; cvta.to.shared.u64 t, %1; cvt.u32.u64 %0, t; }" : "=r"(a) : "l"(p));
    return a;
}
__device__ __forceinline__ void cp_async16(uint32_t saddr, const void* gptr) {
    asm volatile("cp.async.cg.shared.global [%0], [%1], 16;" :: "r"(saddr), "l"(gptr));
}
__device__ __forceinline__ void cp_commit() { asm volatile("cp.async.commit_group;"); }
__device__ __forceinline__ void cp_wait1()  { asm volatile("cp.async.wait_group 1;"); }
__device__ __forceinline__ void cp_wait0()  { asm volatile("cp.async.wait_group 0;"); }

__device__ __forceinline__ void ldsm4(uint32_t& r0, uint32_t& r1, uint32_t& r2, uint32_t& r3,
                                      uint32_t addr) {
    asm volatile("ldmatrix.sync.aligned.m8n8.x4.shared.b16 {%0,%1,%2,%3}, [%4];"
                 : "=r"(r0), "=r"(r1), "=r"(r2), "=r"(r3) : "r"(addr));
}
__device__ __forceinline__ void mma_fp16(float* c, const uint32_t* a, uint32_t b0, uint32_t b1) {
    asm volatile("mma.sync.aligned.m16n8k16.row.col.f32.f16.f16.f32 "
                 "{%0,%1,%2,%3}, {%4,%5,%6,%7}, {%8,%9}, {%0,%1,%2,%3};"
                 : "+f"(c[0]), "+f"(c[1]), "+f"(c[2]), "+f"(c[3])
                 : "r"(a[0]), "r"(a[1]), "r"(a[2]), "r"(a[3]), "r"(b0), "r"(b1));
}

// ---------------------------------------------------------------------------
// Kernel 1: convert + transpose proj -> B[n][k] fp16 (K-major); tiny.
// ---------------------------------------------------------------------------
__global__ void convp_kernel(const float* __restrict__ proj) {
    int n = blockIdx.x, k = threadIdx.x;
    g_bh[n * K_DIM + k] = __float2half_rn(proj[(size_t)k * N_PROJ + n]);
}

// ---------------------------------------------------------------------------
// Kernel 2: single-pass fp16 HMMA GEMM, BM=64 BN=256 BK=64, full grid.
//   Epilogue converts to fp16 and writes PAIRED half2 columns into g_xpt2.
// ---------------------------------------------------------------------------
#define BM 64
#define BN 256
#define BK 64
#define GTHREADS 256
#define S_BOP   16384
#define GEMM_SMEM 81920
#define EPAD 68

__global__ void __launch_bounds__(GTHREADS, 2)
gemm_hmma_kernel(const float* __restrict__ x) {
    extern __shared__ char smem[];
    const uint32_t sb = smem_u32(smem);

    const int t     = threadIdx.x;
    const int lane  = t & 31;
    const int wid   = t >> 5;
    const int mBase = blockIdx.x * BM;
    const int wm    = (wid >> 2) * 32;   // warp tile 32 x 64
    const int wn    = (wid & 3) * 64;

    const int rsel  = lane & 15;
    const int khalf = lane >> 4;
    const int kx    = lane & 7;

    uint32_t mByte[2], nByte[4];
#pragma unroll
    for (int mi = 0; mi < 2; mi++) mByte[mi] = (uint32_t)(wm + mi * 16 + rsel) * 128;
#pragma unroll
    for (int ni = 0; ni < 4; ni++) nByte[ni] = (uint32_t)(wn + ni * 16 + rsel) * 128;

    int aRow[2], aG[2];
    uint32_t aSw[2];
#pragma unroll
    for (int h = 0; h < 2; h++) {
        int u = t + 256 * h;
        aRow[h] = u >> 3;
        aG[h]   = u & 7;
        aSw[h]  = (uint32_t)(aRow[h] * 128 + ((aG[h] ^ (aRow[h] & 7)) << 4));
    }

    float aF[16];
    auto ldgA = [&](int c) {
#pragma unroll
        for (int h = 0; h < 2; h++) {
            const float4* p = (const float4*)(x + (size_t)(mBase + aRow[h]) * K_DIM
                                              + c * BK + aG[h] * 8);
            float4 u0 = p[0], u1 = p[1];
            aF[h*8+0] = u0.x; aF[h*8+1] = u0.y; aF[h*8+2] = u0.z; aF[h*8+3] = u0.w;
            aF[h*8+4] = u1.x; aF[h*8+5] = u1.y; aF[h*8+6] = u1.z; aF[h*8+7] = u1.w;
        }
    };
    auto stsA = [&](int buf) {
#pragma unroll
        for (int h = 0; h < 2; h++) {
            uint32_t pk[4];
#pragma unroll
            for (int j = 0; j < 4; j++) {
                __half2 hh = __floats2half2_rn(aF[h*8 + 2*j], aF[h*8 + 2*j + 1]);
                pk[j] = *(uint32_t*)&hh;
            }
            *(uint4*)(smem + buf * 8192 + aSw[h]) = make_uint4(pk[0], pk[1], pk[2], pk[3]);
        }
    };
    auto cpB = [&](int c) {
        const int kB = c * BK;
        const uint32_t bufB = sb + S_BOP + (c & 1) * 32768;
#pragma unroll
        for (int r = 0; r < 8; r++) {
            int u   = t + GTHREADS * r;
            int row = u >> 3;
            int gg  = u & 7;
            uint32_t sw = (uint32_t)(row * 128 + ((gg ^ (row & 7)) << 4));
            cp_async16(bufB + sw, g_bh + (size_t)row * K_DIM + kB + gg * 8);
        }
        cp_commit();
    };

    float acc[2][8][4];
#pragma unroll
    for (int mi = 0; mi < 2; mi++)
#pragma unroll
        for (int ni = 0; ni < 8; ni++)
#pragma unroll
            for (int r = 0; r < 4; r++) acc[mi][ni][r] = 0.0f;

    ldgA(0);
    cpB(0);
    cpB(1);
    stsA(0);
    ldgA(1);

    const int NCH = K_DIM / BK;   // 4
    for (int c = 0; c < NCH; c++) {
        if (c < NCH - 1) cp_wait1(); else cp_wait0();
        __syncthreads();

        if (c + 1 < NCH) stsA((c + 1) & 1);
        if (c + 2 < NCH) ldgA(c + 2);

        const uint32_t bufA = sb + (c & 1) * 8192;
        const uint32_t bufB = sb + S_BOP + (c & 1) * 32768;

#pragma unroll
        for (int ks = 0; ks < 4; ks++) {
            const uint32_t seg = (uint32_t)((ks * 2 + khalf) ^ kx) << 4;

            uint32_t ah[2][4], bh[4][4];
#pragma unroll
            for (int mi = 0; mi < 2; mi++)
                ldsm4(ah[mi][0], ah[mi][1], ah[mi][2], ah[mi][3], bufA + mByte[mi] + seg);
#pragma unroll
            for (int ni = 0; ni < 4; ni++)
                ldsm4(bh[ni][0], bh[ni][1], bh[ni][2], bh[ni][3], bufB + nByte[ni] + seg);

#pragma unroll
            for (int mi = 0; mi < 2; mi++)
#pragma unroll
                for (int ni = 0; ni < 8; ni++)
                    mma_fp16(acc[mi][ni], ah[mi], bh[ni >> 1][ni & 1], bh[ni >> 1][(ni & 1) + 2]);
        }

        __syncthreads();
        if (c + 2 < NCH) cpB(c + 2);
    }

    // Epilogue: stage D transposed in smem [n][m] fp32 (stride EPAD)
    float* sOut = (float*)smem;
    const int crow = lane >> 2;
    const int ccol = (lane & 3) * 2;
#pragma unroll
    for (int mi = 0; mi < 2; mi++)
#pragma unroll
        for (int ni = 0; ni < 8; ni++) {
            int m0 = wm + mi * 16 + crow;
            int n0 = wn + ni * 8 + ccol;
            sOut[(n0    ) * EPAD + m0    ] = acc[mi][ni][0];
            sOut[(n0 + 1) * EPAD + m0    ] = acc[mi][ni][1];
            sOut[(n0    ) * EPAD + m0 + 8] = acc[mi][ni][2];
            sOut[(n0 + 1) * EPAD + m0 + 8] = acc[mi][ni][3];
        }
    __syncthreads();

    // Paired fp16 write: g_xpt2[(g*128 + p2)*512 + i] = (D[2p2][i], D[2p2+1][i])
    const int g     = mBase >> 9;
    const int iBase = mBase & 511;
#pragma unroll
    for (int r = 0; r < 8; r++) {
        int u  = t + GTHREADS * r;          // 0..2047
        int p2 = u >> 4;                    // 0..127
        int i4 = (u & 15) * 4;              // 0..60
        const float* r0 = &sOut[(2 * p2    ) * EPAD + i4];
        const float* r1 = &sOut[(2 * p2 + 1) * EPAD + i4];
        __half2 h0 = __floats2half2_rn(r0[0], r1[0]);
        __half2 h1 = __floats2half2_rn(r0[1], r1[1]);
        __half2 h2 = __floats2half2_rn(r0[2], r1[2]);
        __half2 h3 = __floats2half2_rn(r0[3], r1[3]);
        __half2* dst = g_xpt2 + ((size_t)(g * 128 + p2)) * NPG + iBase + i4;
        *(uint4*)dst = make_uint4(*(uint32_t*)&h0, *(uint32_t*)&h1,
                                  *(uint32_t*)&h2, *(uint32_t*)&h3);
    }
}

// ---------------------------------------------------------------------------
// Kernel 3: packed half2 bitonic sort (one column-pair per warp), loading the
//   pre-paired g_xpt2 directly (no conversion/packing on load). Full grid.
// ---------------------------------------------------------------------------
__device__ __forceinline__ __half2 h2min(__half2 a, __half2 b) { return __hmin2(a, b); }
__device__ __forceinline__ __half2 h2max(__half2 a, __half2 b) { return __hmax2(a, b); }

template<int KK, int J>
__device__ __forceinline__ void bstep2(__half2 (&v)[16], int lane) {
    if constexpr (J >= 16) {
#pragma unroll
        for (int r = 0; r < 16; r++) {
            uint32_t pv = __shfl_xor_sync(0xffffffffu, *(uint32_t*)&v[r], J >> 4);
            __half2 p = *(__half2*)&pv;
            int i = lane * 16 + r;
            bool takeMin = ((i & KK) == 0) == ((i & J) == 0);
            v[r] = takeMin ? h2min(v[r], p) : h2max(v[r], p);
        }
    } else {
#pragma unroll
        for (int r = 0; r < 16; r++) {
            if ((r & J) == 0) {
                int i = lane * 16 + r;
                bool up = ((i & KK) == 0);
                __half2 a = v[r], b = v[r | J];
                v[r]     = up ? h2min(a, b) : h2max(a, b);
                v[r | J] = up ? h2max(a, b) : h2min(a, b);
            }
        }
    }
}
template<int KK, int J>
__device__ __forceinline__ void bmerge2(__half2 (&v)[16], int lane) {
    bstep2<KK, J>(v, lane);
    if constexpr (J > 1) bmerge2<KK, J / 2>(v, lane);
}

__global__ void __launch_bounds__(256)
sort_quant_kernel(const float* __restrict__ cw, float* __restrict__ out) {
    __shared__ uint32_t sbuf[8][512];   // sorted half2 column-pairs, one per warp
    __shared__ uint32_t qbuf[8][264];   // half2 quantiles staged (padded stride)
    __shared__ int      qidx[NUM_Q];

    const int t = threadIdx.x;
    qidx[t] = (int)floorf(cw[t] * (float)(NPG - 1));   // matches jnp.floor(cw*511)
    __syncthreads();

    const int w    = t >> 5;
    const int lane = t & 31;
    const int unit = blockIdx.x;                       // 16 columns (8 pairs) per unit
    const int p2   = unit * 8 + w;                     // this warp's column pair

    // Direct load of paired fp16 data (element i = lane*16 + r)
    __half2 v[16];
    const uint4* src = (const uint4*)(g_xpt2 + (size_t)p2 * NPG);
#pragma unroll
    for (int q = 0; q < 4; q++) {
        uint4 d = src[lane * 4 + q];
        v[q * 4 + 0] = *(__half2*)&d.x;
        v[q * 4 + 1] = *(__half2*)&d.y;
        v[q * 4 + 2] = *(__half2*)&d.z;
        v[q * 4 + 3] = *(__half2*)&d.w;
    }

    bmerge2<2, 1>(v, lane);
    bmerge2<4, 2>(v, lane);
    bmerge2<8, 4>(v, lane);
    bmerge2<16, 8>(v, lane);
    bmerge2<32, 16>(v, lane);
    bmerge2<64, 32>(v, lane);
    bmerge2<128, 64>(v, lane);
    bmerge2<256, 128>(v, lane);
    bmerge2<512, 256>(v, lane);

    uint4* dst = (uint4*)sbuf[w];
#pragma unroll
    for (int q = 0; q < 4; q++)
        dst[lane * 4 + q] = make_uint4(*(uint32_t*)&v[q * 4 + 0], *(uint32_t*)&v[q * 4 + 1],
                                       *(uint32_t*)&v[q * 4 + 2], *(uint32_t*)&v[q * 4 + 3]);
    __syncwarp();

#pragma unroll
    for (int s = 0; s < 8; s++) {
        int q = lane + 32 * s;
        qbuf[w][q] = sbuf[w][qidx[q]];
    }
    __syncthreads();

    // Coalesced write: out[g*65536 + q*256 + p], 16 consecutive p per CTA
    const int gg    = unit >> 4;
    const int pbase = (unit * 16) & 255;
    const size_t obase = (size_t)gg * (NUM_Q * N_PROJ) + pbase;
#pragma unroll
    for (int s = 0; s < 16; s++) {
        int e  = t + 256 * s;          // 0..4095
        int q  = e >> 4;
        int wp = e & 15;
        uint32_t pair = qbuf[wp >> 1][q];
        __half h = (wp & 1) ? __high2half(*(__half2*)&pair) : __low2half(*(__half2*)&pair);
        out[obase + (size_t)q * N_PROJ + wp] = __half2float(h) * (1.0f / 256.0f);
    }
}

// ---------------------------------------------------------------------------
// kernel_launch: convp -> fp16 gemm (paired epilogue) -> half2 sort; monolithic
// ---------------------------------------------------------------------------
extern "C" void kernel_launch(void* const* d_in, const int* in_sizes, int n_in,
                              void* d_out, int out_size) {
    const float* x    = (const float*)d_in[0];   // [131072, 256] f32
    const float* proj = (const float*)d_in[1];   // [256, 256]    f32
    const float* cw   = (const float*)d_in[2];   // [256]         f32
    float* out = (float*)d_out;                  // [256, 65536]  f32

    cudaFuncSetAttribute(gemm_hmma_kernel,
                         cudaFuncAttributeMaxDynamicSharedMemorySize,
                         GEMM_SMEM);

    convp_kernel<<<N_PROJ, K_DIM>>>(proj);
    gemm_hmma_kernel<<<M_NODES / BM, GTHREADS, GEMM_SMEM>>>(x);
    sort_quant_kernel<<<(NUM_G * N_PROJ) / 16, 256>>>(cw, out);
}